// round 9
// baseline (speedup 1.0000x reference)
#include <cuda_runtime.h>
#include <math_constants.h>
#include <float.h>

#define BB 8
#define QQ 2048
#define GG 128
#define CC 512

#define TLSA 256              // solver threads per block
#define NW   (TLSA / 32)      // warps
#define KC   (QQ / TLSA)      // 8 contiguous columns per thread

// Transposed cost scratch: costT[b][g][q], fp32 (identical bits to final_cost)
__device__ float g_costT[BB * GG * QQ];

// ---------------------------------------------------------------------------
// Kernel 1: fused cost computation + transpose (bit-exact vs reference).
// ---------------------------------------------------------------------------
__global__ __launch_bounds__(256) void cost_kernel(
    const float* __restrict__ prob,     // [B][Q][C]
    const float* __restrict__ center,   // [B][Q][G]
    const float* __restrict__ size_,    // [B][Q][G]
    const float* __restrict__ gious,    // [B][Q][G]
    const void*  __restrict__ labels_v, // [B][G] int32 (default) or int64
    int labels_i64,
    float* __restrict__ fc)             // [B][Q][G]  (output region)
{
    __shared__ float tile[32][33];
    const int b  = blockIdx.z;
    const int g0 = blockIdx.x * 32;
    const int q0 = blockIdx.y * 32;
    const int tx = threadIdx.x;
    const int ty = threadIdx.y;

    const int g = g0 + tx;
    int cls;
    if (labels_i64) cls = (int)((const long long*)labels_v)[b * GG + g];
    else            cls = ((const int*)labels_v)[b * GG + g];

#pragma unroll
    for (int r = 0; r < 4; ++r) {
        const int q = q0 + ty + r * 8;
        const size_t bq = (size_t)b * QQ + q;
        const float x = prob[bq * CC + cls];

        const float p = __fdiv_rn(1.0f, __fadd_rn(1.0f, expf(-x)));

        const float t0  = __fsub_rn(p, 1e-8f);
        const float neg = __fmul_rn(__fmul_rn(0.75f, __fmul_rn(p, p)),
                                    -log1pf(-t0));
        const float omp = __fsub_rn(1.0f, p);
        const float pos = __fmul_rn(__fmul_rn(0.25f, __fmul_rn(omp, omp)),
                                    -logf(__fadd_rn(p, 1e-8f)));
        const float diff = __fsub_rn(pos, neg);

        const size_t idx = bq * GG + g;
        float cost = __fmul_rn(2.0f, diff);
        cost = __fadd_rn(cost, __fmul_rn(5.0f, center[idx]));
        cost = __fadd_rn(cost, __fmul_rn(1.0f, size_[idx]));
        cost = __fadd_rn(cost, __fmul_rn(2.0f, -gious[idx]));

        fc[idx] = cost;
        tile[ty + r * 8][tx] = cost;
    }
    __syncthreads();

#pragma unroll
    for (int r = 0; r < 4; ++r) {
        const int gl = ty + r * 8;
        g_costT[((size_t)b * GG + (g0 + gl)) * QQ + (q0 + tx)] = tile[tx][gl];
    }
}

// ordered-float encode/decode (monotonic u32)
__device__ __forceinline__ unsigned ford(float x) {
    unsigned b = __float_as_uint(x);
    return b ^ ((b & 0x80000000u) ? 0xFFFFFFFFu : 0x80000000u);
}
__device__ __forceinline__ float funord(unsigned k) {
    unsigned b = (k & 0x80000000u) ? (k ^ 0x80000000u) : ~k;
    return __uint_as_float(b);
}

// ---------------------------------------------------------------------------
// Kernel 2: reference degenerate JV. Fast path: column index packed into the
// low byte of a truncated ordered-fp32 key -> two redux.min per warp yield
// (min,col) and second-min with no ballot/shfl. Interval test on truncated
// cells + tau routes ANY possible ordering discrepancy to an exact fp64
// fallback -> selection bit-identical to a pure fp64 scan. Chain sum S is
// accumulated by all threads from a parity-buffered delta broadcast.
// ---------------------------------------------------------------------------
__global__ __launch_bounds__(TLSA, 1) void lsa_kernel(
    const void* __restrict__ nactual_v,
    int n_i64,
    float* __restrict__ out_inds_f32,
    long long* __restrict__ out_inds_i64,
    float* __restrict__ out_mask)
{
    __shared__ double u[GG + 1];
    __shared__ short  p[QQ + 1];
    __shared__ unsigned long long slots[2][NW];
    __shared__ unsigned m2s[2][NW];
    __shared__ double s_delta[2];
    __shared__ double sv[NW];
    __shared__ int    si[NW];
    __shared__ short  ccols[GG + 4];
    __shared__ double cA[GG + 4];

    const int b = blockIdx.x;
    const int t = threadIdx.x;
    int n;
    if (n_i64) n = (int)((const long long*)nactual_v)[b];
    else       n = ((const int*)nactual_v)[b];
    if (n < 0) n = 0;
    if (n > GG) n = GG;

    const float* Cb = g_costT + (size_t)b * GG * QQ;
    const int base = t * KC;            // owns columns base+1 .. base+KC
    const int lane = t & 31;
    const int wix  = t >> 5;
    const unsigned lcolbase = (unsigned)(lane * KC);  // warp-local col base

    double v64[KC];
    float  v32[KC];
#pragma unroll
    for (int k = 0; k < KC; ++k) { v64[k] = 0.0; v32[k] = 0.0f; }

    for (int j = t; j <= QQ; j += TLSA) p[j] = 0;
    for (int i = t; i <= GG; i += TLSA) u[i] = 0.0;
    __syncthreads();

    double UVmax = 0.0;
    const unsigned fm = 0xffffffffu;

    for (int i = 1; i <= n; ++i) {
        unsigned mask = (1u << KC) - 1u;
        int    i0 = i;
        int    hop = 0;
        int    jsel = 0;
        int    lastpw = 0;
        double S = 0.0;
        const float tau = (float)(1.2e-7 * (100.0 + 6.0 * UVmax));

        const float* row0 = Cb + (size_t)(i0 - 1) * QQ + base;
        float4 r0 = *(const float4*)(row0);
        float4 r1 = *(const float4*)(row0 + 4);

        while (true) {
            const int pw = hop & 1;
            const double ui0 = u[i0];
            const float c32[KC] = { r0.x, r0.y, r0.z, r0.w, r1.x, r1.y, r1.z, r1.w };

            // local (min,2nd-min) over packed truncated keys; used cols have
            // v32 = -INF -> w = +INF -> giant key (never wins)
            unsigned key1 = 0xFFFFFFFFu, key2 = 0xFFFFFFFFu;
#pragma unroll
            for (int k = 0; k < KC; ++k) {
                const float w = __fsub_rn(c32[k], v32[k]);
                const unsigned pk2 = (ford(w) & 0xFFFFFF00u) | (lcolbase + k);
                if (pk2 < key1) { key2 = key1; key1 = pk2; }
                else if (pk2 < key2) { key2 = pk2; }
            }

            // warp reduce: min packed (carries col), then second-min
            const unsigned m1 = __reduce_min_sync(fm, key1);
            const unsigned cand2 = (key1 == m1) ? key2 : key1;  // owner unique
            const unsigned m2 = __reduce_min_sync(fm, cand2);

            if (lane == 0) {
                slots[pw][wix] = ((unsigned long long)m1 << 3) | (unsigned)wix;
                m2s[pw][wix] = m2;
            }
            __syncthreads();                       // the single barrier

            if (hop > 0) S += s_delta[pw ^ 1];     // catch up (off crit path)

            // slot tree: global winner + global second-min key
            unsigned long long a0 = slots[pw][0];
#pragma unroll
            for (int wi = 1; wi < NW; ++wi) {
                const unsigned long long x = slots[pw][wi];
                if (x < a0) a0 = x;
            }
            unsigned gsec = 0xFFFFFFFFu;
#pragma unroll
            for (int wi = 0; wi < NW; ++wi) {
                const unsigned long long x = slots[pw][wi];
                const unsigned cnd = (x == a0) ? m2s[pw][wi] : (unsigned)(x >> 3);
                if (cnd < gsec) gsec = cnd;
            }

            const unsigned m1g = (unsigned)(a0 >> 3);
            const int jfast = ((int)(a0 & 7)) * (32 * KC) + (int)(m1g & 0xFFu) + 1;

            int pj = p[jfast];                     // speculative (early LDS)
            if (pj != 0) {                         // speculative prefetch
                const float* nr = Cb + (size_t)(pj - 1) * QQ + base;
                r0 = *(const float4*)(nr);
                r1 = *(const float4*)(nr + 4);
            }

            // interval ambiguity test over truncated cells
            const float gw_hi = funord((m1g & 0xFFFFFF00u) | 0xFFu);
            const float gs_lo = funord(gsec & 0xFFFFFF00u);
            const bool ambig = (gs_lo <= __fadd_rn(gw_hi, tau));

            int jj;
            if (!ambig) {
                jj = jfast;
                if (((jj - 1) >> 3) == t) {        // owner bookkeeping
                    const int k = (jj - 1) & (KC - 1);
                    const double delta = ((double)c32[k] - ui0) - v64[k];
                    s_delta[pw] = delta;
                    if (pj != 0) { ccols[hop] = (short)jj; cA[hop] = S + delta; }
                    v32[k] = -CUDART_INF_F;
                    mask &= ~(1u << k);
                }
            } else {
                // exact full fp64 reduce (rare; uniform branch)
                double best = DBL_MAX; int bestj = 1 << 30;
#pragma unroll
                for (int k = 0; k < KC; ++k) {
                    if ((mask >> k) & 1) {
                        const double cur = ((double)c32[k] - ui0) - v64[k];
                        if (cur < best) { best = cur; bestj = base + k + 1; }
                    }
                }
#pragma unroll
                for (int off = 16; off; off >>= 1) {
                    const double ov = __shfl_down_sync(fm, best, off);
                    const int    oi = __shfl_down_sync(fm, bestj, off);
                    if (ov < best || (ov == best && oi < bestj)) { best = ov; bestj = oi; }
                }
                if (lane == 0) { sv[wix] = best; si[wix] = bestj; }
                __syncthreads();
                double dd = sv[0]; int jjj = si[0];
#pragma unroll
                for (int wi = 1; wi < NW; ++wi) {
                    if (sv[wi] < dd || (sv[wi] == dd && si[wi] < jjj)) { dd = sv[wi]; jjj = si[wi]; }
                }
                __syncthreads();                   // protect sv/si reuse
                jj = jjj;
                pj = p[jj];
                if (pj != 0) {                     // correct the prefetch
                    const float* nr = Cb + (size_t)(pj - 1) * QQ + base;
                    r0 = *(const float4*)(nr);
                    r1 = *(const float4*)(nr + 4);
                }
                if (t == 0) {
                    s_delta[pw] = dd;
                    if (pj != 0) { ccols[hop] = (short)jj; cA[hop] = S + dd; }
                }
                if (((jj - 1) >> 3) == t) {
                    const int k = (jj - 1) & (KC - 1);
                    v32[k] = -CUDART_INF_F;
                    mask &= ~(1u << k);
                }
            }

            if (pj == 0) { jsel = jj; lastpw = pw; break; }
            ++hop;
            i0 = pj;
        }

        // ---- row end (single barrier) ----
        __syncthreads();                           // chain writes visible
        S += s_delta[lastpw];                      // full chain sum
        const int len = hop;
        if (t == 0) { u[i] += S; p[jsel] = (short)i; }
        if (t < len) { u[p[ccols[t]]] += S - cA[t]; }

        double bump = fabs(S);
        for (int c = 0; c < len; ++c) {
            const int    jc  = ccols[c];
            const double adj = S - cA[c];
            bump = fmax(bump, fabs(adj));
            const int rel = jc - 1 - base;
            if (rel >= 0 && rel < KC) {
#pragma unroll
                for (int k = 0; k < KC; ++k)
                    if (rel == k) v64[k] -= adj;
            }
        }
#pragma unroll
        for (int k = 0; k < KC; ++k) v32[k] = (float)v64[k];  // also un-INFs
        UVmax += bump;
        // no closing barrier needed: next row reads u[i+1] (never written
        // here) pre-barrier; p/u/cA/ccols reads occur post next barrier.
    }

    __syncthreads();
    // Emit per-proposal gt index + matched mask
    for (int j = t + 1; j <= QQ; j += TLSA) {
        const int    r = p[j];
        const size_t o = (size_t)b * QQ + (j - 1);
        if (out_inds_f32) out_inds_f32[o] = (r > 0) ? (float)(r - 1) : 0.0f;
        if (out_inds_i64) out_inds_i64[o] = (r > 0) ? (long long)(r - 1) : 0LL;
        out_mask[o] = (r > 0) ? 1.0f : 0.0f;
    }
}

// ---------------------------------------------------------------------------
extern "C" void kernel_launch(void* const* d_in, const int* in_sizes, int n_in,
                              void* d_out, int out_size) {
    const float* prob    = (const float*)d_in[0];
    const float* center  = (const float*)d_in[1];
    const float* size_   = (const float*)d_in[2];
    const float* gious   = (const float*)d_in[3];
    const void*  labels  = d_in[4];
    const void*  nactual = d_in[5];

    float*     out_f32  = (float*)d_out;
    float*     inds_f32 = nullptr;
    long long* inds_i64 = nullptr;
    float*     mask;
    float*     fc;
    int i64_world = 0;

    if (out_size == 2146304) {
        i64_world = 1;
        inds_i64 = (long long*)d_out;
        mask = out_f32 + 32768;
        fc   = out_f32 + 49152;
    } else {
        inds_f32 = out_f32;
        mask = out_f32 + BB * QQ;
        fc   = out_f32 + 2 * BB * QQ;
    }

    dim3 cgrid(GG / 32, QQ / 32, BB);
    dim3 cblk(32, 8);
    cost_kernel<<<cgrid, cblk>>>(prob, center, size_, gious, labels, i64_world, fc);

    lsa_kernel<<<BB, TLSA>>>(nactual, i64_world, inds_f32, inds_i64, mask);
}

// round 10
// speedup vs baseline: 1.5223x; 1.5223x over previous
#include <cuda_runtime.h>
#include <math_constants.h>
#include <float.h>

#define BB 8
#define QQ 2048
#define GG 128
#define CC 512

#define TLSA 256              // solver threads per block
#define NW   (TLSA / 32)      // warps
#define KC   (QQ / TLSA)      // 8 contiguous columns per thread

// Transposed cost scratch: costT[b][g][q], fp32 (identical bits to final_cost)
__device__ float g_costT[BB * GG * QQ];

// ---------------------------------------------------------------------------
// Kernel 1: fused cost computation + transpose (bit-exact vs reference).
// ---------------------------------------------------------------------------
__global__ __launch_bounds__(256) void cost_kernel(
    const float* __restrict__ prob,     // [B][Q][C]
    const float* __restrict__ center,   // [B][Q][G]
    const float* __restrict__ size_,    // [B][Q][G]
    const float* __restrict__ gious,    // [B][Q][G]
    const void*  __restrict__ labels_v, // [B][G] int32 (default) or int64
    int labels_i64,
    float* __restrict__ fc)             // [B][Q][G]  (output region)
{
    __shared__ float tile[32][33];
    const int b  = blockIdx.z;
    const int g0 = blockIdx.x * 32;
    const int q0 = blockIdx.y * 32;
    const int tx = threadIdx.x;
    const int ty = threadIdx.y;

    const int g = g0 + tx;
    int cls;
    if (labels_i64) cls = (int)((const long long*)labels_v)[b * GG + g];
    else            cls = ((const int*)labels_v)[b * GG + g];

#pragma unroll
    for (int r = 0; r < 4; ++r) {
        const int q = q0 + ty + r * 8;
        const size_t bq = (size_t)b * QQ + q;
        const float x = prob[bq * CC + cls];

        const float p = __fdiv_rn(1.0f, __fadd_rn(1.0f, expf(-x)));

        const float t0  = __fsub_rn(p, 1e-8f);
        const float neg = __fmul_rn(__fmul_rn(0.75f, __fmul_rn(p, p)),
                                    -log1pf(-t0));
        const float omp = __fsub_rn(1.0f, p);
        const float pos = __fmul_rn(__fmul_rn(0.25f, __fmul_rn(omp, omp)),
                                    -logf(__fadd_rn(p, 1e-8f)));
        const float diff = __fsub_rn(pos, neg);

        const size_t idx = bq * GG + g;
        float cost = __fmul_rn(2.0f, diff);
        cost = __fadd_rn(cost, __fmul_rn(5.0f, center[idx]));
        cost = __fadd_rn(cost, __fmul_rn(1.0f, size_[idx]));
        cost = __fadd_rn(cost, __fmul_rn(2.0f, -gious[idx]));

        fc[idx] = cost;
        tile[ty + r * 8][tx] = cost;
    }
    __syncthreads();

#pragma unroll
    for (int r = 0; r < 4; ++r) {
        const int gl = ty + r * 8;
        g_costT[((size_t)b * GG + (g0 + gl)) * QQ + (q0 + tx)] = tile[tx][gl];
    }
}

// ordered-float encode/decode (monotonic u32)
__device__ __forceinline__ unsigned ford(float x) {
    unsigned b = __float_as_uint(x);
    return b ^ ((b & 0x80000000u) ? 0xFFFFFFFFu : 0x80000000u);
}
__device__ __forceinline__ float funord(unsigned k) {
    unsigned b = (k & 0x80000000u) ? (k ^ 0x80000000u) : ~k;
    return __uint_as_float(b);
}

// ---------------------------------------------------------------------------
// Kernel 2: reference degenerate JV. Fast path per chain iteration:
//   full-precision ordered-fp32 keys -> redux.min + ballot (min, owner,
//   2nd-min per warp), one barrier, slot tree, speculative p[] + prefetch.
//   Owner broadcasts the exact fp64 delta through parity-buffered s_delta;
//   every thread accumulates the chain sum S after the next barrier.
//   A sound tau-window routes any near-tie to an exact full-fp64 reduce,
//   so selection is bit-identical to a pure fp64 scan.
// ---------------------------------------------------------------------------
__global__ __launch_bounds__(TLSA, 1) void lsa_kernel(
    const void* __restrict__ nactual_v,
    int n_i64,
    float* __restrict__ out_inds_f32,
    long long* __restrict__ out_inds_i64,
    float* __restrict__ out_mask)
{
    __shared__ double u[GG + 1];
    __shared__ short  p[QQ + 1];
    __shared__ unsigned long long slots[2][NW];
    __shared__ unsigned m2s[2][NW];
    __shared__ double s_delta[2];
    __shared__ double sv[NW];
    __shared__ int    si[NW];
    __shared__ short  ccols[GG + 4];
    __shared__ double cA[GG + 4];

    const int b = blockIdx.x;
    const int t = threadIdx.x;
    int n;
    if (n_i64) n = (int)((const long long*)nactual_v)[b];
    else       n = ((const int*)nactual_v)[b];
    if (n < 0) n = 0;
    if (n > GG) n = GG;

    const float* Cb = g_costT + (size_t)b * GG * QQ;
    const int base = t * KC;            // owns columns base+1 .. base+KC
    const int lane = t & 31;
    const int wix  = t >> 5;

    double v64[KC];
    float  v32[KC];
#pragma unroll
    for (int k = 0; k < KC; ++k) { v64[k] = 0.0; v32[k] = 0.0f; }

    for (int j = t; j <= QQ; j += TLSA) p[j] = 0;
    for (int i = t; i <= GG; i += TLSA) u[i] = 0.0;
    __syncthreads();

    double UVmax = 0.0;
    const unsigned fm = 0xffffffffu;

    for (int i = 1; i <= n; ++i) {
        unsigned mask = (1u << KC) - 1u;
        int    i0 = i;
        int    hop = 0;
        int    jsel = 0;
        int    lastpw = 0;
        double S = 0.0;
        const float tau = (float)(1.2e-7 * (100.0 + 6.0 * UVmax));

        const float* row0 = Cb + (size_t)(i0 - 1) * QQ + base;
        float4 r0 = *(const float4*)(row0);
        float4 r1 = *(const float4*)(row0 + 4);

        while (true) {
            const int pw = hop & 1;
            const double ui0 = u[i0];
            const float c32[KC] = { r0.x, r0.y, r0.z, r0.w, r1.x, r1.y, r1.z, r1.w };

            // local (min, 2nd-min) over full ordered keys; used cols have
            // v32 = -INF -> w = +INF -> giant key (never wins)
            unsigned key1 = 0xFFFFFFFFu, key2 = 0xFFFFFFFFu;
            int k1 = 0;
#pragma unroll
            for (int k = 0; k < KC; ++k) {
                const float w = __fsub_rn(c32[k], v32[k]);
                const unsigned kk = ford(w);
                if (kk < key1) { key2 = key1; key1 = kk; k1 = k; }
                else if (kk < key2) { key2 = kk; }
            }

            // warp reduce: min, owner lane (lowest -> smallest col), 2nd-min
            const unsigned m1 = __reduce_min_sync(fm, key1);
            const unsigned ball = __ballot_sync(fm, key1 == m1);
            const int owner_lane = __ffs(ball) - 1;
            const unsigned cand2 = (lane == owner_lane) ? key2 : key1;
            const unsigned m2 = __reduce_min_sync(fm, cand2);
            const int col1 = __shfl_sync(fm, base + k1 + 1, owner_lane);

            if (lane == 0) {
                slots[pw][wix] = ((unsigned long long)m1 << 32) | (unsigned)col1;
                m2s[pw][wix] = m2;
            }
            __syncthreads();                       // the single barrier

            if (hop > 0) S += s_delta[pw ^ 1];     // catch up (off crit path)

            // slot tree: global winner + global second-min key
            unsigned long long a0 = slots[pw][0];
#pragma unroll
            for (int wi = 1; wi < NW; ++wi) {
                const unsigned long long x = slots[pw][wi];
                if (x < a0) a0 = x;
            }
            unsigned gsec = 0xFFFFFFFFu;
#pragma unroll
            for (int wi = 0; wi < NW; ++wi) {
                const unsigned long long x = slots[pw][wi];
                const unsigned cnd = (x == a0) ? m2s[pw][wi] : (unsigned)(x >> 32);
                if (cnd < gsec) gsec = cnd;
            }

            const int jfast = (int)(a0 & 0xffffffffu);

            int pj = p[jfast];                     // speculative (early LDS)
            if (pj != 0) {                         // speculative prefetch
                const float* nr = Cb + (size_t)(pj - 1) * QQ + base;
                r0 = *(const float4*)(nr);
                r1 = *(const float4*)(nr + 4);
            }

            const float gw = funord((unsigned)(a0 >> 32));
            const float gs = funord(gsec);                    // NaN if none
            const bool ambig = (gs <= __fadd_rn(gw, tau));    // NaN -> false

            int jj;
            if (!ambig) {
                jj = jfast;
                if (((jj - 1) >> 3) == t) {        // owner bookkeeping
                    const int k = (jj - 1) & (KC - 1);
                    const double delta = ((double)c32[k] - ui0) - v64[k];
                    s_delta[pw] = delta;
                    if (pj != 0) { ccols[hop] = (short)jj; cA[hop] = S + delta; }
                    v32[k] = -CUDART_INF_F;
                    mask &= ~(1u << k);
                }
            } else {
                // exact full fp64 reduce (rare; uniform branch)
                double best = DBL_MAX; int bestj = 1 << 30;
#pragma unroll
                for (int k = 0; k < KC; ++k) {
                    if ((mask >> k) & 1) {
                        const double cur = ((double)c32[k] - ui0) - v64[k];
                        if (cur < best) { best = cur; bestj = base + k + 1; }
                    }
                }
#pragma unroll
                for (int off = 16; off; off >>= 1) {
                    const double ov = __shfl_down_sync(fm, best, off);
                    const int    oi = __shfl_down_sync(fm, bestj, off);
                    if (ov < best || (ov == best && oi < bestj)) { best = ov; bestj = oi; }
                }
                if (lane == 0) { sv[wix] = best; si[wix] = bestj; }
                __syncthreads();
                double dd = sv[0]; int jjj = si[0];
#pragma unroll
                for (int wi = 1; wi < NW; ++wi) {
                    if (sv[wi] < dd || (sv[wi] == dd && si[wi] < jjj)) { dd = sv[wi]; jjj = si[wi]; }
                }
                __syncthreads();                   // protect sv/si reuse
                jj = jjj;
                pj = p[jj];
                if (pj != 0) {                     // correct the prefetch
                    const float* nr = Cb + (size_t)(pj - 1) * QQ + base;
                    r0 = *(const float4*)(nr);
                    r1 = *(const float4*)(nr + 4);
                }
                if (t == 0) {
                    s_delta[pw] = dd;
                    if (pj != 0) { ccols[hop] = (short)jj; cA[hop] = S + dd; }
                }
                if (((jj - 1) >> 3) == t) {
                    const int k = (jj - 1) & (KC - 1);
                    v32[k] = -CUDART_INF_F;
                    mask &= ~(1u << k);
                }
            }

            if (pj == 0) { jsel = jj; lastpw = pw; break; }
            ++hop;
            i0 = pj;
        }

        // ---- row end (single barrier) ----
        __syncthreads();                           // chain writes visible
        S += s_delta[lastpw];                      // full chain sum
        const int len = hop;
        if (t == 0) { u[i] += S; p[jsel] = (short)i; }
        if (t < len) { u[p[ccols[t]]] += S - cA[t]; }

        double bump = fabs(S);
        for (int c = 0; c < len; ++c) {
            const int    jc  = ccols[c];
            const double adj = S - cA[c];
            bump = fmax(bump, fabs(adj));
            const int rel = jc - 1 - base;
            if (rel >= 0 && rel < KC) {
#pragma unroll
                for (int k = 0; k < KC; ++k)
                    if (rel == k) v64[k] -= adj;
            }
        }
#pragma unroll
        for (int k = 0; k < KC; ++k) v32[k] = (float)v64[k];  // also un-INFs
        UVmax += bump;
        // no closing barrier: all cross-thread consumers of the values
        // written above sit on the far side of the next hop-0 barrier.
    }

    __syncthreads();
    // Emit per-proposal gt index + matched mask
    for (int j = t + 1; j <= QQ; j += TLSA) {
        const int    r = p[j];
        const size_t o = (size_t)b * QQ + (j - 1);
        if (out_inds_f32) out_inds_f32[o] = (r > 0) ? (float)(r - 1) : 0.0f;
        if (out_inds_i64) out_inds_i64[o] = (r > 0) ? (long long)(r - 1) : 0LL;
        out_mask[o] = (r > 0) ? 1.0f : 0.0f;
    }
}

// ---------------------------------------------------------------------------
extern "C" void kernel_launch(void* const* d_in, const int* in_sizes, int n_in,
                              void* d_out, int out_size) {
    const float* prob    = (const float*)d_in[0];
    const float* center  = (const float*)d_in[1];
    const float* size_   = (const float*)d_in[2];
    const float* gious   = (const float*)d_in[3];
    const void*  labels  = d_in[4];
    const void*  nactual = d_in[5];

    float*     out_f32  = (float*)d_out;
    float*     inds_f32 = nullptr;
    long long* inds_i64 = nullptr;
    float*     mask;
    float*     fc;
    int i64_world = 0;

    if (out_size == 2146304) {
        i64_world = 1;
        inds_i64 = (long long*)d_out;
        mask = out_f32 + 32768;
        fc   = out_f32 + 49152;
    } else {
        inds_f32 = out_f32;
        mask = out_f32 + BB * QQ;
        fc   = out_f32 + 2 * BB * QQ;
    }

    dim3 cgrid(GG / 32, QQ / 32, BB);
    dim3 cblk(32, 8);
    cost_kernel<<<cgrid, cblk>>>(prob, center, size_, gious, labels, i64_world, fc);

    lsa_kernel<<<BB, TLSA>>>(nactual, i64_world, inds_f32, inds_i64, mask);
}